// round 1
// baseline (speedup 1.0000x reference)
#include <cuda_runtime.h>
#include <cstdint>

#define N_NODES 50000
#define N_EDGES 800000
#define F_IN    128
#define HDIM    128      // HEADS*HID
#define N_HEADS 8
#define HID     16
#define F_OUT   32
#define NEG_SLOPE 0.2f

// ---------------- device scratch (static globals: no allocation) ----------------
__device__ float g_z1[N_NODES * HDIM];        // layer1 transformed features
__device__ float g_es1[N_NODES * N_HEADS];
__device__ float g_ed1[N_NODES * N_HEADS];
__device__ float g_h1[N_NODES * HDIM];        // layer1 output (post-ELU)
__device__ float g_z2[N_NODES * F_OUT];
__device__ float g_es2[N_NODES];
__device__ float g_ed2[N_NODES];
__device__ int   g_deg[N_NODES];
__device__ int   g_rowptr[N_NODES + 1];
__device__ int   g_cursor[N_NODES];
__device__ int   g_csrsrc[N_EDGES];           // src node per CSR slot (sorted by dst)
__device__ int   g_bsum[256];

// ---------------- CSR build ----------------
__global__ void k_zero_deg() {
    int i = blockIdx.x * 256 + threadIdx.x;
    if (i < N_NODES) g_deg[i] = 0;
}

__global__ void k_hist(const int* __restrict__ dst) {
    int e = blockIdx.x * 256 + threadIdx.x;
    if (e < N_EDGES) atomicAdd(&g_deg[dst[e]], 1);
}

__global__ void k_scan_a() {
    __shared__ int sh[256];
    int i = blockIdx.x * 256 + threadIdx.x;
    int v = (i < N_NODES) ? g_deg[i] : 0;
    sh[threadIdx.x] = v;
    __syncthreads();
    for (int off = 128; off > 0; off >>= 1) {
        if (threadIdx.x < off) sh[threadIdx.x] += sh[threadIdx.x + off];
        __syncthreads();
    }
    if (threadIdx.x == 0) g_bsum[blockIdx.x] = sh[0];
}

__global__ void k_scan_b() {
    __shared__ int sh[256];
    int t = threadIdx.x;
    int nb = (N_NODES + 255) / 256;
    int v = (t < nb) ? g_bsum[t] : 0;
    sh[t] = v;
    __syncthreads();
    for (int off = 1; off < 256; off <<= 1) {
        int a = (t >= off) ? sh[t - off] : 0;
        __syncthreads();
        sh[t] += a;
        __syncthreads();
    }
    g_bsum[t] = sh[t] - v;   // exclusive
}

__global__ void k_scan_c() {
    __shared__ int sh[256];
    int t = threadIdx.x;
    int i = blockIdx.x * 256 + t;
    int v = (i < N_NODES) ? g_deg[i] : 0;
    sh[t] = v;
    __syncthreads();
    for (int off = 1; off < 256; off <<= 1) {
        int a = (t >= off) ? sh[t - off] : 0;
        __syncthreads();
        sh[t] += a;
        __syncthreads();
    }
    int excl = g_bsum[blockIdx.x] + sh[t] - v;
    if (i < N_NODES) {
        g_rowptr[i] = excl;
        g_cursor[i] = excl;
    }
    if (i == 0) g_rowptr[N_NODES] = N_EDGES;
}

__global__ void k_scatter(const int* __restrict__ src, const int* __restrict__ dst) {
    int e = blockIdx.x * 256 + threadIdx.x;
    if (e < N_EDGES) {
        int p = atomicAdd(&g_cursor[dst[e]], 1);
        g_csrsrc[p] = src[e];
    }
}

// ---------------- tiled fp32 GEMM: C[M,BN] = A[M,128] * B[128,BN] ----------------
template <int BN, int TM, int TN>
__global__ void __launch_bounds__((128 / TM) * (BN / TN))
k_gemm(const float* __restrict__ A, const float* __restrict__ B,
       float* __restrict__ C, int M) {
    constexpr int BM = 128, K = 128, PAD = 4;
    constexpr int TX = BN / TN;
    constexpr int NT = (BM / TM) * TX;
    extern __shared__ float smem[];
    float* sA = smem;                    // [K][BM+PAD]  (transposed A tile)
    float* sB = smem + K * (BM + PAD);   // [K][BN]
    const int tid = threadIdx.x;
    const int row0 = blockIdx.x * BM;

    for (int i = tid; i < K * BN; i += NT) sB[i] = B[i];
    for (int i = tid; i < BM * K; i += NT) {
        int k = i & (K - 1);
        int r = i >> 7;
        int row = row0 + r;
        sA[k * (BM + PAD) + r] = (row < M) ? A[(size_t)row * K + k] : 0.f;
    }
    __syncthreads();

    const int tn = (tid % TX) * TN;
    const int tm = (tid / TX) * TM;
    float acc[TM][TN];
#pragma unroll
    for (int i = 0; i < TM; i++)
#pragma unroll
        for (int j = 0; j < TN; j++) acc[i][j] = 0.f;

#pragma unroll 4
    for (int k = 0; k < K; k++) {
        float a[TM], b[TN];
#pragma unroll
        for (int i = 0; i < TM; i += 4)
            *(float4*)&a[i] = *(const float4*)&sA[k * (BM + PAD) + tm + i];
#pragma unroll
        for (int j = 0; j < TN; j += 4)
            *(float4*)&b[j] = *(const float4*)&sB[k * BN + tn + j];
#pragma unroll
        for (int i = 0; i < TM; i++)
#pragma unroll
            for (int j = 0; j < TN; j++) acc[i][j] += a[i] * b[j];
    }

#pragma unroll
    for (int i = 0; i < TM; i++) {
        int row = row0 + tm + i;
        if (row < M) {
            float* cp = C + (size_t)row * BN + tn;
#pragma unroll
            for (int j = 0; j < TN; j += 4)
                *(float4*)&cp[j] = *(const float4*)&acc[i][j];
        }
    }
}

// ---------------- per-node attention dots ----------------
__global__ void k_dots1(const float* __restrict__ as, const float* __restrict__ ad) {
    int idx = blockIdx.x * 256 + threadIdx.x;
    if (idx >= N_NODES * N_HEADS) return;
    int n = idx >> 3, h = idx & 7;
    const float* zp = g_z1 + (size_t)n * HDIM + h * HID;
    const float* ap = as + h * HID;
    const float* bp = ad + h * HID;
    float es = 0.f, ed = 0.f;
#pragma unroll
    for (int d = 0; d < HID; d++) {
        float z = zp[d];
        es += z * ap[d];
        ed += z * bp[d];
    }
    g_es1[idx] = es;
    g_ed1[idx] = ed;
}

__global__ void k_dots2(const float* __restrict__ as, const float* __restrict__ ad) {
    int n = blockIdx.x * 256 + threadIdx.x;
    if (n >= N_NODES) return;
    const float* zp = g_z2 + (size_t)n * F_OUT;
    float es = 0.f, ed = 0.f;
#pragma unroll
    for (int d = 0; d < F_OUT; d++) {
        float z = zp[d];
        es += z * as[d];
        ed += z * ad[d];
    }
    g_es2[n] = es;
    g_ed2[n] = ed;
}

// ---------------- layer1 aggregation: warp per dst node, softmax fused, ELU fused ----------------
__global__ void k_agg1() {
    int n = (blockIdx.x * blockDim.x + threadIdx.x) >> 5;
    int lane = threadIdx.x & 31;
    if (n >= N_NODES) return;
    int beg = g_rowptr[n], end = g_rowptr[n + 1];
    float edh = (lane < 8) ? g_ed1[n * 8 + lane] : 0.f;
    float acc0 = 0.f, acc1 = 0.f, acc2 = 0.f, acc3 = 0.f, ssum = 0.f;
    const int hb = lane >> 4;  // 0 or 1

    for (int base = beg; base < end; base += 32) {
        int cnt = end - base;
        if (cnt > 32) cnt = 32;
        int sv = (base + lane < end) ? g_csrsrc[base + lane] : 0;
        for (int j = 0; j < cnt; ++j) {
            int s = __shfl_sync(0xffffffffu, sv, j);
            float w = 0.f;
            if (lane < 8) {
                float t = g_es1[s * 8 + lane] + edh;
                t = (t >= 0.f) ? t : NEG_SLOPE * t;
                w = __expf(t);
                ssum += w;
            }
            float w0 = __shfl_sync(0xffffffffu, w, hb);
            float w1 = __shfl_sync(0xffffffffu, w, hb + 2);
            float w2 = __shfl_sync(0xffffffffu, w, hb + 4);
            float w3 = __shfl_sync(0xffffffffu, w, hb + 6);
            const float* zp = g_z1 + (size_t)s * HDIM;
            acc0 += w0 * zp[lane];
            acc1 += w1 * zp[lane + 32];
            acc2 += w2 * zp[lane + 64];
            acc3 += w3 * zp[lane + 96];
        }
    }

    float S0 = __shfl_sync(0xffffffffu, ssum, hb);
    float S1 = __shfl_sync(0xffffffffu, ssum, hb + 2);
    float S2 = __shfl_sync(0xffffffffu, ssum, hb + 4);
    float S3 = __shfl_sync(0xffffffffu, ssum, hb + 6);
    float r0 = 0.f, r1 = 0.f, r2 = 0.f, r3 = 0.f;
    if (end > beg) {
        r0 = acc0 / S0; r1 = acc1 / S1; r2 = acc2 / S2; r3 = acc3 / S3;
    }
    // ELU
    r0 = (r0 > 0.f) ? r0 : expm1f(r0);
    r1 = (r1 > 0.f) ? r1 : expm1f(r1);
    r2 = (r2 > 0.f) ? r2 : expm1f(r2);
    r3 = (r3 > 0.f) ? r3 : expm1f(r3);
    float* op = g_h1 + (size_t)n * HDIM;
    op[lane] = r0;
    op[lane + 32] = r1;
    op[lane + 64] = r2;
    op[lane + 96] = r3;
}

// ---------------- layer2 aggregation: warp per dst node, single head ----------------
__global__ void k_agg2(float* __restrict__ out) {
    int n = (blockIdx.x * blockDim.x + threadIdx.x) >> 5;
    int lane = threadIdx.x & 31;
    if (n >= N_NODES) return;
    int beg = g_rowptr[n], end = g_rowptr[n + 1];
    float ed = g_ed2[n];
    float acc = 0.f, S = 0.f;

    for (int base = beg; base < end; base += 32) {
        int cnt = end - base;
        if (cnt > 32) cnt = 32;
        int sv = (base + lane < end) ? g_csrsrc[base + lane] : 0;
        for (int j = 0; j < cnt; ++j) {
            int s = __shfl_sync(0xffffffffu, sv, j);
            float t = g_es2[s] + ed;
            t = (t >= 0.f) ? t : NEG_SLOPE * t;
            float w = __expf(t);
            S += w;
            acc += w * g_z2[(size_t)s * F_OUT + lane];
        }
    }
    out[(size_t)n * F_OUT + lane] = (end > beg) ? (acc / S) : 0.f;
}

// ---------------- launch ----------------
extern "C" void kernel_launch(void* const* d_in, const int* in_sizes, int n_in,
                              void* d_out, int out_size) {
    const float* h   = (const float*)d_in[0];
    const float* W1  = (const float*)d_in[1];
    const float* a1s = (const float*)d_in[2];
    const float* a1d = (const float*)d_in[3];
    const float* W2  = (const float*)d_in[4];
    const float* a2s = (const float*)d_in[5];
    const float* a2d = (const float*)d_in[6];
    const int*   src = (const int*)d_in[7];
    const int*   dst = (const int*)d_in[8];
    float* out = (float*)d_out;

    void *z1p, *h1p, *z2p;
    cudaGetSymbolAddress(&z1p, g_z1);
    cudaGetSymbolAddress(&h1p, g_h1);
    cudaGetSymbolAddress(&z2p, g_z2);

    constexpr int SM1 = (128 * 132 + 128 * 128) * 4;  // 133120 B
    constexpr int SM2 = (128 * 132 + 128 * 32) * 4;   // 83968 B
    cudaFuncSetAttribute(k_gemm<128, 8, 8>, cudaFuncAttributeMaxDynamicSharedMemorySize, SM1);
    cudaFuncSetAttribute(k_gemm<32, 8, 4>,  cudaFuncAttributeMaxDynamicSharedMemorySize, SM2);

    const int nb_n = (N_NODES + 255) / 256;   // 196
    const int nb_e = (N_EDGES + 255) / 256;   // 3125
    const int nb_g = (N_NODES + 127) / 128;   // 391
    const int nb_w = (N_NODES + 7) / 8;       // 6250 (8 warps/block)

    // CSR build (by dst)
    k_zero_deg<<<nb_n, 256>>>();
    k_hist<<<nb_e, 256>>>(dst);
    k_scan_a<<<nb_n, 256>>>();
    k_scan_b<<<1, 256>>>();
    k_scan_c<<<nb_n, 256>>>();
    k_scatter<<<nb_e, 256>>>(src, dst);

    // layer 1
    k_gemm<128, 8, 8><<<nb_g, 256, SM1>>>(h, W1, (float*)z1p, N_NODES);
    k_dots1<<<(N_NODES * N_HEADS + 255) / 256, 256>>>(a1s, a1d);
    k_agg1<<<nb_w, 256>>>();

    // layer 2
    k_gemm<32, 8, 4><<<nb_g, 128, SM2>>>((const float*)h1p, W2, (float*)z2p, N_NODES);
    k_dots2<<<nb_n, 256>>>(a2s, a2d);
    k_agg2<<<nb_w, 256>>>(out);
}

// round 2
// speedup vs baseline: 1.0522x; 1.0522x over previous
#include <cuda_runtime.h>
#include <cstdint>

#define N_NODES 50000
#define N_EDGES 800000
#define F_IN    128
#define HDIM    128      // HEADS*HID
#define N_HEADS 8
#define HID     16
#define F_OUT   32
#define NEG_SLOPE 0.2f

typedef unsigned long long u64t;

__device__ __forceinline__ void ffma2(u64t& d, u64t a, u64t b) {
    asm("fma.rn.f32x2 %0, %1, %2, %3;" : "=l"(d) : "l"(a), "l"(b), "l"(d));
}
__device__ __forceinline__ u64t dup2(float a) {
    u64t d; asm("mov.b64 %0, {%1, %1};" : "=l"(d) : "f"(a)); return d;
}

// ---------------- device scratch ----------------
__device__ float g_z1[N_NODES * HDIM];
__device__ float g_es1[N_NODES * N_HEADS];
__device__ float g_ed1[N_NODES * N_HEADS];
__device__ float g_h1[N_NODES * HDIM];
__device__ float g_z2[N_NODES * F_OUT];
__device__ float g_es2[N_NODES];
__device__ float g_ed2[N_NODES];
__device__ int   g_deg[N_NODES];
__device__ int   g_rowptr[N_NODES + 1];
__device__ int   g_cursor[N_NODES];
__device__ int   g_csrsrc[N_EDGES];
__device__ int   g_bsum[256];

// ---------------- CSR build ----------------
__global__ void k_zero_deg() {
    int i = blockIdx.x * 256 + threadIdx.x;
    if (i < N_NODES) g_deg[i] = 0;
}

__global__ void k_hist(const int* __restrict__ dst) {
    int e = blockIdx.x * 256 + threadIdx.x;
    if (e < N_EDGES) atomicAdd(&g_deg[dst[e]], 1);
}

__global__ void k_scan_a() {
    __shared__ int sh[256];
    int i = blockIdx.x * 256 + threadIdx.x;
    int v = (i < N_NODES) ? g_deg[i] : 0;
    sh[threadIdx.x] = v;
    __syncthreads();
    for (int off = 128; off > 0; off >>= 1) {
        if (threadIdx.x < off) sh[threadIdx.x] += sh[threadIdx.x + off];
        __syncthreads();
    }
    if (threadIdx.x == 0) g_bsum[blockIdx.x] = sh[0];
}

__global__ void k_scan_b() {
    __shared__ int sh[256];
    int t = threadIdx.x;
    int nb = (N_NODES + 255) / 256;
    int v = (t < nb) ? g_bsum[t] : 0;
    sh[t] = v;
    __syncthreads();
    for (int off = 1; off < 256; off <<= 1) {
        int a = (t >= off) ? sh[t - off] : 0;
        __syncthreads();
        sh[t] += a;
        __syncthreads();
    }
    g_bsum[t] = sh[t] - v;   // exclusive
}

__global__ void k_scan_c() {
    __shared__ int sh[256];
    int t = threadIdx.x;
    int i = blockIdx.x * 256 + t;
    int v = (i < N_NODES) ? g_deg[i] : 0;
    sh[t] = v;
    __syncthreads();
    for (int off = 1; off < 256; off <<= 1) {
        int a = (t >= off) ? sh[t - off] : 0;
        __syncthreads();
        sh[t] += a;
        __syncthreads();
    }
    int excl = g_bsum[blockIdx.x] + sh[t] - v;
    if (i < N_NODES) {
        g_rowptr[i] = excl;
        g_cursor[i] = excl;
    }
    if (i == 0) g_rowptr[N_NODES] = N_EDGES;
}

__global__ void k_scatter(const int* __restrict__ src, const int* __restrict__ dst) {
    int e = blockIdx.x * 256 + threadIdx.x;
    if (e < N_EDGES) {
        int p = atomicAdd(&g_cursor[dst[e]], 1);
        g_csrsrc[p] = src[e];
    }
}

// ---------------- tiled GEMM with packed f32x2 FMA ----------------
template <int BN, int TM, int TN>
__global__ void __launch_bounds__((128 / TM) * (BN / TN))
k_gemm(const float* __restrict__ A, const float* __restrict__ B,
       float* __restrict__ C, int M) {
    constexpr int BM = 128, K = 128, PAD = 4;
    constexpr int TX = BN / TN;
    constexpr int NT = (BM / TM) * TX;
    extern __shared__ float smem[];
    float* sA = smem;                    // [K][BM+PAD]
    float* sB = smem + K * (BM + PAD);   // [K][BN]
    const int tid = threadIdx.x;
    const int row0 = blockIdx.x * BM;

    for (int i = tid; i < K * BN; i += NT) sB[i] = B[i];
    for (int i = tid; i < BM * K; i += NT) {
        int k = i & (K - 1);
        int r = i >> 7;
        int row = row0 + r;
        sA[k * (BM + PAD) + r] = (row < M) ? A[(size_t)row * K + k] : 0.f;
    }
    __syncthreads();

    const int tn = (tid % TX) * TN;
    const int tm = (tid / TX) * TM;
    u64t acc[TM][TN / 2];
#pragma unroll
    for (int i = 0; i < TM; i++)
#pragma unroll
        for (int j = 0; j < TN / 2; j++) acc[i][j] = 0ULL;

#pragma unroll 4
    for (int k = 0; k < K; k++) {
        float a[TM];
#pragma unroll
        for (int i = 0; i < TM; i += 4)
            *(float4*)&a[i] = *(const float4*)&sA[k * (BM + PAD) + tm + i];
        u64t b2[TN / 2];
        const u64t* bp = (const u64t*)&sB[k * BN + tn];
#pragma unroll
        for (int j = 0; j < TN / 2; j++) b2[j] = bp[j];
        u64t a2[TM];
#pragma unroll
        for (int i = 0; i < TM; i++) a2[i] = dup2(a[i]);
#pragma unroll
        for (int i = 0; i < TM; i++)
#pragma unroll
            for (int j = 0; j < TN / 2; j++) ffma2(acc[i][j], a2[i], b2[j]);
    }

#pragma unroll
    for (int i = 0; i < TM; i++) {
        int row = row0 + tm + i;
        if (row < M) {
            float* cp = C + (size_t)row * BN + tn;
#pragma unroll
            for (int j = 0; j < TN / 2; j++)
                *(u64t*)&cp[j * 2] = acc[i][j];
        }
    }
}

// ---------------- per-node attention dots ----------------
__global__ void k_dots1(const float* __restrict__ as, const float* __restrict__ ad) {
    int idx = blockIdx.x * 256 + threadIdx.x;
    if (idx >= N_NODES * N_HEADS) return;
    int n = idx >> 3, h = idx & 7;
    const float* zp = g_z1 + (size_t)n * HDIM + h * HID;
    const float* ap = as + h * HID;
    const float* bp = ad + h * HID;
    float es = 0.f, ed = 0.f;
#pragma unroll
    for (int d = 0; d < HID; d += 4) {
        float4 z = *(const float4*)&zp[d];
        float4 av = *(const float4*)&ap[d];
        float4 bv = *(const float4*)&bp[d];
        es += z.x * av.x + z.y * av.y + z.z * av.z + z.w * av.w;
        ed += z.x * bv.x + z.y * bv.y + z.z * bv.z + z.w * bv.w;
    }
    g_es1[idx] = es;
    g_ed1[idx] = ed;
}

__global__ void k_dots2(const float* __restrict__ as, const float* __restrict__ ad) {
    int n = blockIdx.x * 256 + threadIdx.x;
    if (n >= N_NODES) return;
    const float* zp = g_z2 + (size_t)n * F_OUT;
    float es = 0.f, ed = 0.f;
#pragma unroll
    for (int d = 0; d < F_OUT; d += 4) {
        float4 z = *(const float4*)&zp[d];
        float4 av = *(const float4*)&as[d];
        float4 bv = *(const float4*)&ad[d];
        es += z.x * av.x + z.y * av.y + z.z * av.z + z.w * av.w;
        ed += z.x * bv.x + z.y * bv.y + z.z * bv.z + z.w * bv.w;
    }
    g_es2[n] = es;
    g_ed2[n] = ed;
}

// ---------------- layer1 aggregation: lane-parallel weights + unrolled gather ----------------
__global__ void __launch_bounds__(256) k_agg1() {
    __shared__ int   ss[8][32];
    __shared__ float ws[8][8][33];   // [warp][head][edge]
    const int w = threadIdx.x >> 5;
    const int lane = threadIdx.x & 31;
    const int n = blockIdx.x * 8 + w;
    if (n >= N_NODES) return;
    const int beg = g_rowptr[n], end = g_rowptr[n + 1];
    const int hb = lane >> 4;

    float ed[8];
    {
        float4 lo = *(const float4*)&g_ed1[n * 8];
        float4 hi = *(const float4*)&g_ed1[n * 8 + 4];
        ed[0] = lo.x; ed[1] = lo.y; ed[2] = lo.z; ed[3] = lo.w;
        ed[4] = hi.x; ed[5] = hi.y; ed[6] = hi.z; ed[7] = hi.w;
    }

    float acc0 = 0.f, acc1 = 0.f, acc2 = 0.f, acc3 = 0.f;
    float ssum[8];
#pragma unroll
    for (int h = 0; h < 8; h++) ssum[h] = 0.f;

    for (int base = beg; base < end; base += 32) {
        const int cnt = min(32, end - base);
        float wv[8];
        int sv = 0;
        if (lane < cnt) {
            sv = g_csrsrc[base + lane];
            float4 lo = *(const float4*)&g_es1[sv * 8];
            float4 hi = *(const float4*)&g_es1[sv * 8 + 4];
            float es[8] = {lo.x, lo.y, lo.z, lo.w, hi.x, hi.y, hi.z, hi.w};
#pragma unroll
            for (int h = 0; h < 8; h++) {
                float t = es[h] + ed[h];
                t = (t >= 0.f) ? t : NEG_SLOPE * t;
                wv[h] = __expf(t);
                ssum[h] += wv[h];
            }
        } else {
#pragma unroll
            for (int h = 0; h < 8; h++) wv[h] = 0.f;
        }
        ss[w][lane] = sv;
#pragma unroll
        for (int h = 0; h < 8; h++) ws[w][h][lane] = wv[h];
        __syncwarp();

        int j = 0;
        for (; j + 4 <= cnt; j += 4) {
#pragma unroll
            for (int u = 0; u < 4; u++) {
                int s = ss[w][j + u];
                const float* zp = g_z1 + (size_t)s * HDIM;
                float w0 = ws[w][hb][j + u];
                float w1 = ws[w][hb + 2][j + u];
                float w2 = ws[w][hb + 4][j + u];
                float w3 = ws[w][hb + 6][j + u];
                acc0 += w0 * zp[lane];
                acc1 += w1 * zp[lane + 32];
                acc2 += w2 * zp[lane + 64];
                acc3 += w3 * zp[lane + 96];
            }
        }
        for (; j < cnt; j++) {
            int s = ss[w][j];
            const float* zp = g_z1 + (size_t)s * HDIM;
            acc0 += ws[w][hb][j]     * zp[lane];
            acc1 += ws[w][hb + 2][j] * zp[lane + 32];
            acc2 += ws[w][hb + 4][j] * zp[lane + 64];
            acc3 += ws[w][hb + 6][j] * zp[lane + 96];
        }
        __syncwarp();
    }

    // warp-reduce per-head sums
#pragma unroll
    for (int h = 0; h < 8; h++)
#pragma unroll
        for (int off = 16; off; off >>= 1)
            ssum[h] += __shfl_xor_sync(0xffffffffu, ssum[h], off);

    float r0 = 0.f, r1 = 0.f, r2 = 0.f, r3 = 0.f;
    if (end > beg) {
        r0 = acc0 / ssum[hb];
        r1 = acc1 / ssum[hb + 2];
        r2 = acc2 / ssum[hb + 4];
        r3 = acc3 / ssum[hb + 6];
    }
    r0 = (r0 > 0.f) ? r0 : expm1f(r0);
    r1 = (r1 > 0.f) ? r1 : expm1f(r1);
    r2 = (r2 > 0.f) ? r2 : expm1f(r2);
    r3 = (r3 > 0.f) ? r3 : expm1f(r3);
    float* op = g_h1 + (size_t)n * HDIM;
    op[lane] = r0;
    op[lane + 32] = r1;
    op[lane + 64] = r2;
    op[lane + 96] = r3;
}

// ---------------- layer2 aggregation ----------------
__global__ void __launch_bounds__(256) k_agg2(float* __restrict__ out) {
    __shared__ int   ss[8][32];
    __shared__ float ws[8][33];
    const int w = threadIdx.x >> 5;
    const int lane = threadIdx.x & 31;
    const int n = blockIdx.x * 8 + w;
    if (n >= N_NODES) return;
    const int beg = g_rowptr[n], end = g_rowptr[n + 1];
    const float ed = g_ed2[n];
    float acc = 0.f, S = 0.f;

    for (int base = beg; base < end; base += 32) {
        const int cnt = min(32, end - base);
        float wv = 0.f;
        int sv = 0;
        if (lane < cnt) {
            sv = g_csrsrc[base + lane];
            float t = g_es2[sv] + ed;
            t = (t >= 0.f) ? t : NEG_SLOPE * t;
            wv = __expf(t);
            S += wv;
        }
        ss[w][lane] = sv;
        ws[w][lane] = wv;
        __syncwarp();

        int j = 0;
        for (; j + 4 <= cnt; j += 4) {
#pragma unroll
            for (int u = 0; u < 4; u++) {
                int s = ss[w][j + u];
                acc += ws[w][j + u] * g_z2[(size_t)s * F_OUT + lane];
            }
        }
        for (; j < cnt; j++)
            acc += ws[w][j] * g_z2[(size_t)ss[w][j] * F_OUT + lane];
        __syncwarp();
    }

#pragma unroll
    for (int off = 16; off; off >>= 1)
        S += __shfl_xor_sync(0xffffffffu, S, off);

    out[(size_t)n * F_OUT + lane] = (end > beg) ? (acc / S) : 0.f;
}

// ---------------- launch ----------------
extern "C" void kernel_launch(void* const* d_in, const int* in_sizes, int n_in,
                              void* d_out, int out_size) {
    const float* h   = (const float*)d_in[0];
    const float* W1  = (const float*)d_in[1];
    const float* a1s = (const float*)d_in[2];
    const float* a1d = (const float*)d_in[3];
    const float* W2  = (const float*)d_in[4];
    const float* a2s = (const float*)d_in[5];
    const float* a2d = (const float*)d_in[6];
    const int*   src = (const int*)d_in[7];
    const int*   dst = (const int*)d_in[8];
    float* out = (float*)d_out;

    void *z1p, *h1p, *z2p;
    cudaGetSymbolAddress(&z1p, g_z1);
    cudaGetSymbolAddress(&h1p, g_h1);
    cudaGetSymbolAddress(&z2p, g_z2);

    constexpr int SM1 = (128 * 132 + 128 * 128) * 4;
    constexpr int SM2 = (128 * 132 + 128 * 32) * 4;
    cudaFuncSetAttribute(k_gemm<128, 8, 8>, cudaFuncAttributeMaxDynamicSharedMemorySize, SM1);
    cudaFuncSetAttribute(k_gemm<32, 8, 4>,  cudaFuncAttributeMaxDynamicSharedMemorySize, SM2);

    const int nb_n = (N_NODES + 255) / 256;
    const int nb_e = (N_EDGES + 255) / 256;
    const int nb_g = (N_NODES + 127) / 128;
    const int nb_w = (N_NODES + 7) / 8;

    // CSR build (by dst)
    k_zero_deg<<<nb_n, 256>>>();
    k_hist<<<nb_e, 256>>>(dst);
    k_scan_a<<<nb_n, 256>>>();
    k_scan_b<<<1, 256>>>();
    k_scan_c<<<nb_n, 256>>>();
    k_scatter<<<nb_e, 256>>>(src, dst);

    // layer 1
    k_gemm<128, 8, 8><<<nb_g, 256, SM1>>>(h, W1, (float*)z1p, N_NODES);
    k_dots1<<<(N_NODES * N_HEADS + 255) / 256, 256>>>(a1s, a1d);
    k_agg1<<<nb_w, 256>>>();

    // layer 2
    k_gemm<32, 8, 4><<<nb_g, 128, SM2>>>((const float*)h1p, W2, (float*)z2p, N_NODES);
    k_dots2<<<nb_n, 256>>>(a2s, a2d);
    k_agg2<<<nb_w, 256>>>(out);
}